// round 7
// baseline (speedup 1.0000x reference)
#include <cuda_runtime.h>
#include <cstdint>
#include <math.h>

// Problem constants: W=num_walks=10, L=walk_length=10, D=64 neighbors.
#define W_WALKS 10
#define L_STEPS 10
#define DNB 64
#define FULLMASK 0xFFFFFFFFu

#define EPSf 1e-10f
#define REL_GAP 1e-4f          // relative guard band (fast errors ~1e-5)
#define MASKED_R_MAX 8.5e-4f   // EPS / e_min, e_min = -log1p(-2^-23) ~ 1.192e-7

struct StepKeys {
    unsigned a[L_STEPS];
    unsigned b[L_STEPS];
};

// ---------------------------------------------------------------------------
// Threefry-2x32 (20 rounds), matching jax._src.prng.threefry2x32 exactly.
// ---------------------------------------------------------------------------
__host__ __device__ __forceinline__ void threefry2x32(
    unsigned k0, unsigned k1, unsigned x0, unsigned x1,
    unsigned& o0, unsigned& o1)
{
    unsigned k2 = k0 ^ k1 ^ 0x1BD11BDAu;
    x0 += k0; x1 += k1;
#if defined(__CUDA_ARCH__)
#define TF_ROT(x, r) __funnelshift_l((x), (x), (r))
#else
#define TF_ROT(x, r) (((x) << (r)) | ((x) >> (32 - (r))))
#endif
#define TF_ROUND(r) { x0 += x1; x1 = TF_ROT(x1, r); x1 ^= x0; }
    TF_ROUND(13) TF_ROUND(15) TF_ROUND(26) TF_ROUND(6)
    x0 += k1; x1 += k2 + 1u;
    TF_ROUND(17) TF_ROUND(29) TF_ROUND(16) TF_ROUND(24)
    x0 += k2; x1 += k0 + 2u;
    TF_ROUND(13) TF_ROUND(15) TF_ROUND(26) TF_ROUND(6)
    x0 += k0; x1 += k1 + 3u;
    TF_ROUND(17) TF_ROUND(29) TF_ROUND(16) TF_ROUND(24)
    x0 += k1; x1 += k2 + 4u;
    TF_ROUND(13) TF_ROUND(15) TF_ROUND(26) TF_ROUND(6)
    x0 += k2; x1 += k0 + 5u;
#undef TF_ROUND
#undef TF_ROT
    o0 = x0; o1 = x1;
}

// Partitionable threefry bits: element i -> counter (0, i), output o0^o1.
__device__ __forceinline__ unsigned random_bits_partitionable(
    unsigned ka, unsigned kb, unsigned idx)
{
    unsigned o0, o1;
    threefry2x32(ka, kb, 0u, idx, o0, o1);
    return o0 ^ o1;
}

// bits -> u in [tiny, 1-2^-23], exactly as jax.random.uniform f32 path.
__device__ __forceinline__ float uniform_from_bits(unsigned bits)
{
    const float tiny = 1.17549435082228750797e-38f;
    unsigned m = (bits >> 9) | 0x3f800000u;
    float u = __uint_as_float(m) - 1.0f;
    u = u + tiny;
    return fmaxf(tiny, u);
}

// Fast e = -log(u), rel err ~3e-6 everywhere:
//  u >= 0.5: e = 2*atanh(z), z=(1-u)/(1+u) <= 1/3 (1-u exact by Sterbenz);
//            5-term odd series, trunc err (1/3)^10/11 ~ 1.5e-6 rel.
//  u <  0.5: |log u| >= 0.693 so __logf's ~1.6e-7 abs is rel <= 2.4e-7.
__device__ __forceinline__ float e_from_bits(unsigned bits)
{
    float u = uniform_from_bits(bits);
    float lg = -__logf(u);
    float z = __fdividef(1.0f - u, 1.0f + u);
    float y = z * z;
    float p = fmaf(y, fmaf(y, fmaf(y, fmaf(y, 0.111111111f, 0.142857143f),
                                   0.2f), 0.333333333f), 1.0f);
    return (u >= 0.5f) ? (2.0f * z * p) : lg;
}

// Exact gumbel (double-evaluated, correctly-rounded f32 intermediates).
__device__ __forceinline__ float gumbel_exact(unsigned bits)
{
    float u = uniform_from_bits(bits);
    float l1 = (float)log((double)u);
    float l2 = (float)log((double)(-l1));
    return -l2;
}

// ---------------------------------------------------------------------------
// Cold path: bit-exact reference recomputation of one step's argmax.
// Lane owns elements lane and lane+32. Warp-uniform entry.
// ---------------------------------------------------------------------------
__device__ __noinline__ int exact_argmax(
    float tL, float tH, bool vL, bool vH, int lane,
    unsigned ka, unsigned kb, unsigned ebase64)
{
    const float LOG_EPS_EXACT = (float)log((double)EPSf);

    // true tmax over all 64 (unmasked), where(tmax>0, tmax, 1)
    float m = fmaxf(tL, tH);
    #pragma unroll
    for (int o = 16; o; o >>= 1)
        m = fmaxf(m, __shfl_xor_sync(FULLMASK, m, o));
    const float tmax = (m > 0.0f) ? m : 1.0f;

    float ewL = 0.0f, ewH = 0.0f;
    if (vL) {
        float s = (float)((double)(tL - tmax) / (double)0.1f);
        ewL = (float)exp((double)s);
    }
    if (vH) {
        float s = (float)((double)(tH - tmax) / (double)0.1f);
        ewH = (float)exp((double)s);
    }
    double dsum = (double)ewL + (double)ewH;
    #pragma unroll
    for (int o = 16; o; o >>= 1)
        dsum += __shfl_xor_sync(FULLMASK, dsum, o);
    dsum = __shfl_sync(FULLMASK, dsum, 0);
    const float denom = (float)dsum + EPSf;

    float scL, scH;
    {
        float g = gumbel_exact(random_bits_partitionable(ka, kb, ebase64 + lane));
        float lp;
        if (vL) {
            float p = (float)((double)ewL / (double)denom);
            lp = (float)log((double)(p + EPSf));
        } else lp = LOG_EPS_EXACT;
        scL = lp + g;
    }
    {
        float g = gumbel_exact(random_bits_partitionable(ka, kb, ebase64 + lane + 32));
        float lp;
        if (vH) {
            float p = (float)((double)ewH / (double)denom);
            lp = (float)log((double)(p + EPSf));
        } else lp = LOG_EPS_EXACT;
        scH = lp + g;
    }

    // argmax, first-index tie-break (jnp.argmax semantics)
    float bs; int bix;
    if (scH > scL) { bs = scH; bix = lane + 32; }
    else           { bs = scL; bix = lane; }
    #pragma unroll
    for (int o = 16; o; o >>= 1) {
        float os = __shfl_xor_sync(FULLMASK, bs, o);
        int   oi = __shfl_xor_sync(FULLMASK, bix, o);
        if (os > bs || (os == bs && oi < bix)) { bs = os; bix = oi; }
    }
    return __shfl_sync(FULLMASK, bix, 0);
}

// ---------------------------------------------------------------------------
// One warp per walk. Lane L owns elements d=L and d=L+32.
// ---------------------------------------------------------------------------
__global__ void __launch_bounds__(256)
walk_kernel(const int* __restrict__ src_nodes,
            const float* __restrict__ cur_times,
            const int* __restrict__ nb_ids,
            const float* __restrict__ nb_times,
            float* __restrict__ out,
            int B, StepKeys keys)
{
    const int gwarp = (int)((blockIdx.x * blockDim.x + threadIdx.x) >> 5);
    const int lane = (int)(threadIdx.x & 31);
    const int nwalks = B * W_WALKS;
    if (gwarp >= nwalks) return;

    const int b = gwarp / W_WALKS;

    int   curr  = src_nodes[b];
    float ctime = cur_times[b];
    bool  alive = true;

    const size_t BWL = (size_t)nwalks * L_STEPS;
    float* out_nodes = out;
    float* out_times = out + BWL;
    float* out_masks = out + 2 * BWL;
    const size_t base = (size_t)gwarp * L_STEPS;

    const unsigned ebase64 = (unsigned)gwarp * DNB;

    if (lane == 0) {
        out_nodes[base] = (float)curr;
        out_times[base] = ctime;
        out_masks[base] = 1.0f;
    }

    #pragma unroll 1
    for (int step = 1; step < L_STEPS; step++) {
        if (alive) {
            const size_t row = (size_t)curr * DNB;
            const int   idL = nb_ids[row + lane];
            const int   idH = nb_ids[row + lane + 32];
            const float tL  = nb_times[row + lane];
            const float tH  = nb_times[row + lane + 32];

            const bool vL = (tL < ctime);
            const bool vH = (tH < ctime);
            const unsigned bLv = __ballot_sync(FULLMASK, vL);
            const unsigned bHv = __ballot_sync(FULLMASK, vH);
            const int nL = __popc(bLv);
            const int nvalid = nL + __popc(bHv);

            if (nvalid == 0) {
                alive = false;
            } else {
                const unsigned ka = keys.a[step];
                const unsigned kb = keys.b[step];

                float wL = vL ? __expf((tL - ctime) * 10.0f) : 0.0f;
                float wH = vH ? __expf((tH - ctime) * 10.0f) : 0.0f;

                float ssum = wL + wH;
                #pragma unroll
                for (int o = 16; o; o >>= 1)
                    ssum += __shfl_xor_sync(FULLMASK, ssum, o);
                const float rden = __fdividef(1.0f, ssum + EPSf);

                int bi = -1;

                if (nvalid <= 32) {
                    // ---- COMPACTED: lane i < nvalid owns the i-th valid
                    // element (element order). ONE threefry per lane.
                    // Masked elements unscored; thr > MASKED_R_MAX proves
                    // they cannot win nor reach the guard band.
                    int d = 0;
                    if (lane < nvalid) {
                        d = (lane < nL)
                            ? (int)__fns(bLv, 0, lane + 1)
                            : 32 + (int)__fns(bHv, 0, lane - nL + 1);
                    }
                    // fetch w_d from its owner lane (d per-lane -> 2 shfls)
                    const float wLs = __shfl_sync(FULLMASK, wL, d & 31);
                    const float wHs = __shfl_sync(FULLMASK, wH, d & 31);
                    const float wd  = (d >= 32) ? wHs : wLs;

                    float r = -1.0f;
                    if (lane < nvalid) {
                        float e = e_from_bits(random_bits_partitionable(
                            ka, kb, ebase64 + (unsigned)d));
                        r = __fdividef(fmaf(wd, rden, EPSf), e);
                    }

                    float best = r;
                    #pragma unroll
                    for (int o = 16; o; o >>= 1)
                        best = fmaxf(best, __shfl_xor_sync(FULLMASK, best, o));

                    const float thr = best * (1.0f - REL_GAP);
                    const unsigned bb = __ballot_sync(FULLMASK, r >= thr);
                    if (__popc(bb) == 1 && thr > MASKED_R_MAX)
                        bi = __shfl_sync(FULLMASK, d, __ffs(bb) - 1);
                } else {
                    // ---- FULL: both elements per lane. Masked elements get
                    // r = EPS/e (exactly the reference surrogate) for free.
                    const float eL = e_from_bits(random_bits_partitionable(
                        ka, kb, ebase64 + (unsigned)lane));
                    const float eH = e_from_bits(random_bits_partitionable(
                        ka, kb, ebase64 + (unsigned)lane + 32u));
                    const float rL = __fdividef(fmaf(wL, rden, EPSf), eL);
                    const float rH = __fdividef(fmaf(wH, rden, EPSf), eH);

                    float best = fmaxf(rL, rH);
                    #pragma unroll
                    for (int o = 16; o; o >>= 1)
                        best = fmaxf(best, __shfl_xor_sync(FULLMASK, best, o));

                    const float thr = best * (1.0f - REL_GAP);
                    const unsigned bbL = __ballot_sync(FULLMASK, rL >= thr);
                    const unsigned bbH = __ballot_sync(FULLMASK, rH >= thr);
                    if (__popc(bbL) + __popc(bbH) == 1)
                        bi = bbL ? (__ffs(bbL) - 1) : (32 + __ffs(bbH) - 1);
                }

                if (bi < 0)  // warp-uniform: guard failed -> bit-exact path
                    bi = exact_argmax(tL, tH, vL, vH, lane, ka, kb, ebase64);

                // fetch chosen neighbor (bi warp-uniform -> slot uniform)
                const bool  hi  = (bi >= 32);
                const int   nid = __shfl_sync(FULLMASK, hi ? idH : idL, bi & 31);
                const float nt  = __shfl_sync(FULLMASK, hi ? tH  : tL,  bi & 31);

                curr = nid;
                ctime = nt;
            }
        }

        if (lane == 0) {
            out_nodes[base + step] = (float)curr;
            out_times[base + step] = ctime;
            out_masks[base + step] = alive ? 1.0f : 0.0f;
        }
    }
}

// ---------------------------------------------------------------------------
extern "C" void kernel_launch(void* const* d_in, const int* in_sizes, int n_in,
                              void* d_out, int out_size)
{
    const int*   src = (const int*)d_in[0];
    const float* ct  = (const float*)d_in[1];
    const int*   nid = (const int*)d_in[2];
    const float* nt  = (const float*)d_in[3];
    const int B = in_sizes[0];

    // fold_in(key(42), step) = threefry2x32((0,42), (0,step))
    StepKeys keys;
    for (int s = 0; s < L_STEPS; s++) { keys.a[s] = 0; keys.b[s] = 0; }
    for (int s = 1; s < L_STEPS; s++) {
        unsigned o0, o1;
        threefry2x32(0u, 42u, 0u, (unsigned)s, o0, o1);
        keys.a[s] = o0; keys.b[s] = o1;
    }

    const int nwalks = B * W_WALKS;
    const int threads = 256;
    const int total_threads = nwalks * 32;
    const int blocks = (total_threads + threads - 1) / threads;

    walk_kernel<<<blocks, threads>>>(src, ct, nid, nt, (float*)d_out, B, keys);
}

// round 8
// speedup vs baseline: 1.2689x; 1.2689x over previous
#include <cuda_runtime.h>
#include <cstdint>
#include <math.h>

// Problem constants: W=num_walks=10, L=walk_length=10, D=64 neighbors.
#define W_WALKS 10
#define L_STEPS 10
#define DNB 64
#define FULLMASK 0xFFFFFFFFu

#define EPSf 1e-10f
#define REL_GAP 1e-4f          // relative guard band (fast errors ~1e-5)

struct StepKeys {
    unsigned a[L_STEPS];
    unsigned b[L_STEPS];
};

// ---------------------------------------------------------------------------
// Threefry-2x32 (20 rounds), matching jax._src.prng.threefry2x32 exactly.
// ---------------------------------------------------------------------------
__host__ __device__ __forceinline__ void threefry2x32(
    unsigned k0, unsigned k1, unsigned x0, unsigned x1,
    unsigned& o0, unsigned& o1)
{
    unsigned k2 = k0 ^ k1 ^ 0x1BD11BDAu;
    x0 += k0; x1 += k1;
#if defined(__CUDA_ARCH__)
#define TF_ROT(x, r) __funnelshift_l((x), (x), (r))
#else
#define TF_ROT(x, r) (((x) << (r)) | ((x) >> (32 - (r))))
#endif
#define TF_ROUND(r) { x0 += x1; x1 = TF_ROT(x1, r); x1 ^= x0; }
    TF_ROUND(13) TF_ROUND(15) TF_ROUND(26) TF_ROUND(6)
    x0 += k1; x1 += k2 + 1u;
    TF_ROUND(17) TF_ROUND(29) TF_ROUND(16) TF_ROUND(24)
    x0 += k2; x1 += k0 + 2u;
    TF_ROUND(13) TF_ROUND(15) TF_ROUND(26) TF_ROUND(6)
    x0 += k0; x1 += k1 + 3u;
    TF_ROUND(17) TF_ROUND(29) TF_ROUND(16) TF_ROUND(24)
    x0 += k1; x1 += k2 + 4u;
    TF_ROUND(13) TF_ROUND(15) TF_ROUND(26) TF_ROUND(6)
    x0 += k2; x1 += k0 + 5u;
#undef TF_ROUND
#undef TF_ROT
    o0 = x0; o1 = x1;
}

// Partitionable threefry bits: element i -> counter (0, i), output o0^o1.
__device__ __forceinline__ unsigned random_bits_partitionable(
    unsigned ka, unsigned kb, unsigned idx)
{
    unsigned o0, o1;
    threefry2x32(ka, kb, 0u, idx, o0, o1);
    return o0 ^ o1;
}

// bits -> u, fast form: fmax(f-1, tiny) == ((f-1)+tiny, then fmax) exactly
// (for f-1 > 0 the +tiny is absorbed by rounding; at 0 both give tiny).
__device__ __forceinline__ float uniform_fast(unsigned bits)
{
    const float tiny = 1.17549435082228750797e-38f;
    unsigned m = (bits >> 9) | 0x3f800000u;
    return fmaxf(__uint_as_float(m) - 1.0f, tiny);
}

// Fast e = -log(u), rel err < ~3e-6 everywhere:
//  u >= 27/32: e = 2*atanh(z), z=(1-u)/(1+u) <= 0.0847 (1-u exact, Sterbenz);
//              p = 1 + y/3 + y^2/5, trunc z^6/7 ~ 5e-8 rel.
//  u <  27/32: e >= 0.1699, __logf abs err ~5e-7 -> rel <= 3e-6.
__device__ __forceinline__ float e_from_bits(unsigned bits)
{
    float u = uniform_fast(bits);
    float lg = -__logf(u);
    float z = __fdividef(1.0f - u, 1.0f + u);
    float y = z * z;
    float p = fmaf(y, fmaf(y, 0.2f, 0.33333333333f), 1.0f);
    return (u >= 0.84375f) ? (2.0f * z * p) : lg;
}

// Exact uniform + gumbel (double-evaluated, correctly-rounded f32 chain).
__device__ __forceinline__ float uniform_exact(unsigned bits)
{
    const float tiny = 1.17549435082228750797e-38f;
    unsigned m = (bits >> 9) | 0x3f800000u;
    float u = __uint_as_float(m) - 1.0f;
    u = u + tiny;
    return fmaxf(tiny, u);
}
__device__ __forceinline__ float gumbel_exact(unsigned bits)
{
    float u = uniform_exact(bits);
    float l1 = (float)log((double)u);
    float l2 = (float)log((double)(-l1));
    return -l2;
}

// ---------------------------------------------------------------------------
// Cold path: bit-exact reference recomputation of one step's argmax.
// Lane owns elements d0=2*lane and d0+1. Warp-uniform entry.
// ---------------------------------------------------------------------------
__device__ __noinline__ int exact_argmax(
    float t0, float t1, bool v0, bool v1,
    unsigned ka, unsigned kb, unsigned ebase, int d0)
{
    const float LOG_EPS_EXACT = (float)log((double)EPSf);

    // true tmax over all 64 (unmasked), where(tmax>0, tmax, 1)
    float m = fmaxf(t0, t1);
    #pragma unroll
    for (int o = 16; o; o >>= 1)
        m = fmaxf(m, __shfl_xor_sync(FULLMASK, m, o));
    const float tmax = (m > 0.0f) ? m : 1.0f;

    float ew0 = 0.0f, ew1 = 0.0f;
    if (v0) {
        float s = (float)((double)(t0 - tmax) / (double)0.1f);
        ew0 = (float)exp((double)s);
    }
    if (v1) {
        float s = (float)((double)(t1 - tmax) / (double)0.1f);
        ew1 = (float)exp((double)s);
    }
    double dsum = (double)ew0 + (double)ew1;
    #pragma unroll
    for (int o = 16; o; o >>= 1)
        dsum += __shfl_xor_sync(FULLMASK, dsum, o);
    dsum = __shfl_sync(FULLMASK, dsum, 0);
    const float denom = (float)dsum + EPSf;

    float sc0, sc1;
    {
        float g = gumbel_exact(random_bits_partitionable(ka, kb, ebase));
        float lp;
        if (v0) {
            float p = (float)((double)ew0 / (double)denom);
            lp = (float)log((double)(p + EPSf));
        } else lp = LOG_EPS_EXACT;
        sc0 = lp + g;
    }
    {
        float g = gumbel_exact(random_bits_partitionable(ka, kb, ebase + 1u));
        float lp;
        if (v1) {
            float p = (float)((double)ew1 / (double)denom);
            lp = (float)log((double)(p + EPSf));
        } else lp = LOG_EPS_EXACT;
        sc1 = lp + g;
    }

    // argmax, first-index tie-break (jnp.argmax semantics)
    float bs; int bix;
    if (sc1 > sc0) { bs = sc1; bix = d0 + 1; }
    else           { bs = sc0; bix = d0; }
    #pragma unroll
    for (int o = 16; o; o >>= 1) {
        float os = __shfl_xor_sync(FULLMASK, bs, o);
        int   oi = __shfl_xor_sync(FULLMASK, bix, o);
        if (os > bs || (os == bs && oi < bix)) { bs = os; bix = oi; }
    }
    return __shfl_sync(FULLMASK, bix, 0);
}

// ---------------------------------------------------------------------------
// One warp per walk. Lane L owns elements d=2L and d=2L+1 (vector loads).
// ---------------------------------------------------------------------------
__global__ void __launch_bounds__(128)
walk_kernel(const int* __restrict__ src_nodes,
            const float* __restrict__ cur_times,
            const int* __restrict__ nb_ids,
            const float* __restrict__ nb_times,
            float* __restrict__ out,
            int B, StepKeys keys)
{
    const int gwarp = (int)((blockIdx.x * blockDim.x + threadIdx.x) >> 5);
    const int lane = (int)(threadIdx.x & 31);
    const int nwalks = B * W_WALKS;
    if (gwarp >= nwalks) return;

    const int b = gwarp / W_WALKS;

    int   curr  = src_nodes[b];
    float ctime = cur_times[b];
    bool  alive = true;

    const size_t BWL = (size_t)nwalks * L_STEPS;
    float* out_nodes = out;
    float* out_times = out + BWL;
    float* out_masks = out + 2 * BWL;
    const size_t base = (size_t)gwarp * L_STEPS;

    const int d0 = lane << 1;
    const unsigned ebase = (unsigned)gwarp * DNB + (unsigned)d0;

    if (lane == 0) {
        out_nodes[base] = (float)curr;
        out_times[base] = ctime;
        out_masks[base] = 1.0f;
    }

    #pragma unroll 1
    for (int step = 1; step < L_STEPS; step++) {
        if (alive) {
            const size_t row = (size_t)curr * DNB;
            const int2   ids = reinterpret_cast<const int2*>(nb_ids + row)[lane];
            const float2 ts  = reinterpret_cast<const float2*>(nb_times + row)[lane];
            const float t0 = ts.x, t1 = ts.y;

            const bool v0 = (t0 < ctime);
            const bool v1 = (t1 < ctime);

            if (!__any_sync(FULLMASK, v0 || v1)) {
                alive = false;
            } else {
                const unsigned ka = keys.a[step];
                const unsigned kb = keys.b[step];

                // Gumbel denominators: independent of the gathers above, so
                // this ~170-inst ALU block overlaps the L2 latency.
                const float e0 = e_from_bits(random_bits_partitionable(ka, kb, ebase));
                const float e1 = e_from_bits(random_bits_partitionable(ka, kb, ebase + 1u));

                // exp2 with fused 10*log2(e); ctime-centered (frame factor is
                // warp-uniform -> argmax-neutral, fp error <= ~3e-6 rel).
                float w0 = v0 ? exp2f((t0 - ctime) * 14.4269504089f) : 0.0f;
                float w1 = v1 ? exp2f((t1 - ctime) * 14.4269504089f) : 0.0f;

                float ssum = w0 + w1;
                #pragma unroll
                for (int o = 16; o; o >>= 1)
                    ssum += __shfl_xor_sync(FULLMASK, ssum, o);

                // Surrogate scaled by warp-uniform (S+EPS) > 0:
                //   score ∝ (w_d + EPS*(S+EPS)) / e_d
                // identical argmax to reference in real arithmetic; masked
                // elements (w=0) included automatically.
                const float c = EPSf * (ssum + EPSf);
                const float r0 = __fdividef(w0 + c, e0);
                const float r1 = __fdividef(w1 + c, e1);

                // warp max via REDUX (r >= 0 so uint bit-order == float order)
                const unsigned bmax = __reduce_max_sync(
                    FULLMASK, __float_as_uint(fmaxf(r0, r1)));
                const float thr = __uint_as_float(bmax) * (1.0f - REL_GAP);

                const unsigned b0 = __ballot_sync(FULLMASK, r0 >= thr);
                const unsigned b1 = __ballot_sync(FULLMASK, r1 >= thr);

                int bi;
                if (__popc(b0) + __popc(b1) == 1) {
                    // unique element within the guard band == exact argmax
                    bi = b0 ? ((__ffs(b0) - 1) << 1)
                            : (((__ffs(b1) - 1) << 1) | 1);
                } else {
                    bi = exact_argmax(t0, t1, v0, v1, ka, kb, ebase, d0);
                }

                // fetch chosen neighbor from its owner lane (bi warp-uniform)
                const int   slot = (bi & 1);
                const int   nid = __shfl_sync(FULLMASK, slot ? ids.y : ids.x, bi >> 1);
                const float nt  = __shfl_sync(FULLMASK, slot ? t1    : t0,   bi >> 1);

                curr = nid;
                ctime = nt;
            }
        }

        if (lane == 0) {
            out_nodes[base + step] = (float)curr;
            out_times[base + step] = ctime;
            out_masks[base + step] = alive ? 1.0f : 0.0f;
        }
    }
}

// ---------------------------------------------------------------------------
extern "C" void kernel_launch(void* const* d_in, const int* in_sizes, int n_in,
                              void* d_out, int out_size)
{
    const int*   src = (const int*)d_in[0];
    const float* ct  = (const float*)d_in[1];
    const int*   nid = (const int*)d_in[2];
    const float* nt  = (const float*)d_in[3];
    const int B = in_sizes[0];

    // fold_in(key(42), step) = threefry2x32((0,42), (0,step))
    StepKeys keys;
    for (int s = 0; s < L_STEPS; s++) { keys.a[s] = 0; keys.b[s] = 0; }
    for (int s = 1; s < L_STEPS; s++) {
        unsigned o0, o1;
        threefry2x32(0u, 42u, 0u, (unsigned)s, o0, o1);
        keys.a[s] = o0; keys.b[s] = o1;
    }

    const int nwalks = B * W_WALKS;
    const int threads = 128;
    const int total_threads = nwalks * 32;
    const int blocks = (total_threads + threads - 1) / threads;

    walk_kernel<<<blocks, threads>>>(src, ct, nid, nt, (float*)d_out, B, keys);
}

// round 9
// speedup vs baseline: 1.3114x; 1.0335x over previous
#include <cuda_runtime.h>
#include <cstdint>
#include <math.h>

// Problem constants: W=num_walks=10, L=walk_length=10, D=64 neighbors.
#define W_WALKS 10
#define L_STEPS 10
#define DNB 64
#define FULLMASK 0xFFFFFFFFu

#define EPSf 1e-10f
#define REL_GAP 1e-4f          // relative guard band (fast errors ~1e-5)
// masked surrogate bound: r_masked = c/e <= c / (-log1p(-2^-23)) = c*8.389e6
#define MASKED_C_MULT 8.5e6f

struct StepKeys {
    unsigned a[L_STEPS];
    unsigned b[L_STEPS];
};

// ---------------------------------------------------------------------------
// Threefry-2x32 (20 rounds), matching jax._src.prng.threefry2x32 exactly.
// ---------------------------------------------------------------------------
__host__ __device__ __forceinline__ void threefry2x32(
    unsigned k0, unsigned k1, unsigned x0, unsigned x1,
    unsigned& o0, unsigned& o1)
{
    unsigned k2 = k0 ^ k1 ^ 0x1BD11BDAu;
    x0 += k0; x1 += k1;
#if defined(__CUDA_ARCH__)
#define TF_ROT(x, r) __funnelshift_l((x), (x), (r))
#else
#define TF_ROT(x, r) (((x) << (r)) | ((x) >> (32 - (r))))
#endif
#define TF_ROUND(r) { x0 += x1; x1 = TF_ROT(x1, r); x1 ^= x0; }
    TF_ROUND(13) TF_ROUND(15) TF_ROUND(26) TF_ROUND(6)
    x0 += k1; x1 += k2 + 1u;
    TF_ROUND(17) TF_ROUND(29) TF_ROUND(16) TF_ROUND(24)
    x0 += k2; x1 += k0 + 2u;
    TF_ROUND(13) TF_ROUND(15) TF_ROUND(26) TF_ROUND(6)
    x0 += k0; x1 += k1 + 3u;
    TF_ROUND(17) TF_ROUND(29) TF_ROUND(16) TF_ROUND(24)
    x0 += k1; x1 += k2 + 4u;
    TF_ROUND(13) TF_ROUND(15) TF_ROUND(26) TF_ROUND(6)
    x0 += k2; x1 += k0 + 5u;
#undef TF_ROUND
#undef TF_ROT
    o0 = x0; o1 = x1;
}

// Partitionable threefry bits: element i -> counter (0, i), output o0^o1.
__device__ __forceinline__ unsigned random_bits_partitionable(
    unsigned ka, unsigned kb, unsigned idx)
{
    unsigned o0, o1;
    threefry2x32(ka, kb, 0u, idx, o0, o1);
    return o0 ^ o1;
}

// bits -> u, fast form: fmax(f-1, tiny) == reference chain exactly.
__device__ __forceinline__ float uniform_fast(unsigned bits)
{
    const float tiny = 1.17549435082228750797e-38f;
    unsigned m = (bits >> 9) | 0x3f800000u;
    return fmaxf(__uint_as_float(m) - 1.0f, tiny);
}

// Fast e = -log(u), rel err < ~3e-6 everywhere (atanh branch keeps relative
// accuracy as u -> 1 where e -> 0).
__device__ __forceinline__ float e_from_bits(unsigned bits)
{
    float u = uniform_fast(bits);
    float lg = -__logf(u);
    float z = __fdividef(1.0f - u, 1.0f + u);
    float y = z * z;
    float p = fmaf(y, fmaf(y, 0.2f, 0.33333333333f), 1.0f);
    return (u >= 0.84375f) ? (2.0f * z * p) : lg;
}

// Exact uniform + gumbel (double-evaluated, correctly-rounded f32 chain).
__device__ __forceinline__ float uniform_exact(unsigned bits)
{
    const float tiny = 1.17549435082228750797e-38f;
    unsigned m = (bits >> 9) | 0x3f800000u;
    float u = __uint_as_float(m) - 1.0f;
    u = u + tiny;
    return fmaxf(tiny, u);
}
__device__ __forceinline__ float gumbel_exact(unsigned bits)
{
    float u = uniform_exact(bits);
    float l1 = (float)log((double)u);
    float l2 = (float)log((double)(-l1));
    return -l2;
}

// ---------------------------------------------------------------------------
// Cold path: bit-exact reference recomputation of one step's argmax.
// Lane owns elements d0=2*lane and d0+1. Warp-uniform entry.
// ---------------------------------------------------------------------------
__device__ __noinline__ int exact_argmax(
    float t0, float t1, bool v0, bool v1,
    unsigned ka, unsigned kb, unsigned ebase, int d0)
{
    const float LOG_EPS_EXACT = (float)log((double)EPSf);

    float m = fmaxf(t0, t1);
    #pragma unroll
    for (int o = 16; o; o >>= 1)
        m = fmaxf(m, __shfl_xor_sync(FULLMASK, m, o));
    const float tmax = (m > 0.0f) ? m : 1.0f;

    float ew0 = 0.0f, ew1 = 0.0f;
    if (v0) {
        float s = (float)((double)(t0 - tmax) / (double)0.1f);
        ew0 = (float)exp((double)s);
    }
    if (v1) {
        float s = (float)((double)(t1 - tmax) / (double)0.1f);
        ew1 = (float)exp((double)s);
    }
    double dsum = (double)ew0 + (double)ew1;
    #pragma unroll
    for (int o = 16; o; o >>= 1)
        dsum += __shfl_xor_sync(FULLMASK, dsum, o);
    dsum = __shfl_sync(FULLMASK, dsum, 0);
    const float denom = (float)dsum + EPSf;

    float sc0, sc1;
    {
        float g = gumbel_exact(random_bits_partitionable(ka, kb, ebase));
        float lp;
        if (v0) {
            float p = (float)((double)ew0 / (double)denom);
            lp = (float)log((double)(p + EPSf));
        } else lp = LOG_EPS_EXACT;
        sc0 = lp + g;
    }
    {
        float g = gumbel_exact(random_bits_partitionable(ka, kb, ebase + 1u));
        float lp;
        if (v1) {
            float p = (float)((double)ew1 / (double)denom);
            lp = (float)log((double)(p + EPSf));
        } else lp = LOG_EPS_EXACT;
        sc1 = lp + g;
    }

    float bs; int bix;
    if (sc1 > sc0) { bs = sc1; bix = d0 + 1; }
    else           { bs = sc0; bix = d0; }
    #pragma unroll
    for (int o = 16; o; o >>= 1) {
        float os = __shfl_xor_sync(FULLMASK, bs, o);
        int   oi = __shfl_xor_sync(FULLMASK, bix, o);
        if (os > bs || (os == bs && oi < bix)) { bs = os; bix = oi; }
    }
    return __shfl_sync(FULLMASK, bix, 0);
}

// ---------------------------------------------------------------------------
// One warp per walk. Lane L owns elements d=2L and d=2L+1 (vector loads).
// When nvalid <= 32, valid elements are rank-compacted onto lanes via smem
// so each lane runs ONE threefry instead of two.
// ---------------------------------------------------------------------------
__global__ void __launch_bounds__(128)
walk_kernel(const int* __restrict__ src_nodes,
            const float* __restrict__ cur_times,
            const int* __restrict__ nb_ids,
            const float* __restrict__ nb_times,
            float* __restrict__ out,
            int B, StepKeys keys)
{
    __shared__ int s_d[4][32];   // per-warp compaction buffer

    const int gwarp = (int)((blockIdx.x * blockDim.x + threadIdx.x) >> 5);
    const int lane = (int)(threadIdx.x & 31);
    const int wwarp = (int)(threadIdx.x >> 5);
    const int nwalks = B * W_WALKS;
    if (gwarp >= nwalks) return;

    const int b = gwarp / W_WALKS;

    int   curr  = src_nodes[b];
    float ctime = cur_times[b];
    bool  alive = true;

    const size_t BWL = (size_t)nwalks * L_STEPS;
    float* out_nodes = out;
    float* out_times = out + BWL;
    float* out_masks = out + 2 * BWL;
    const size_t base = (size_t)gwarp * L_STEPS;

    const int d0 = lane << 1;
    const unsigned ebase64 = (unsigned)gwarp * DNB;
    const unsigned ebase = ebase64 + (unsigned)d0;
    const unsigned ltmask = (1u << lane) - 1u;

    if (lane == 0) {
        out_nodes[base] = (float)curr;
        out_times[base] = ctime;
        out_masks[base] = 1.0f;
    }

    #pragma unroll 1
    for (int step = 1; step < L_STEPS; step++) {
        if (alive) {
            const size_t row = (size_t)curr * DNB;
            const int2   ids = reinterpret_cast<const int2*>(nb_ids + row)[lane];
            const float2 ts  = reinterpret_cast<const float2*>(nb_times + row)[lane];
            const float t0 = ts.x, t1 = ts.y;

            const bool v0 = (t0 < ctime);
            const bool v1 = (t1 < ctime);
            const unsigned bL = __ballot_sync(FULLMASK, v0);
            const unsigned bH = __ballot_sync(FULLMASK, v1);
            const int nvalid = __popc(bL) + __popc(bH);

            if (nvalid == 0) {
                alive = false;
            } else {
                const unsigned ka = keys.a[step];
                const unsigned kb = keys.b[step];

                // weights, ctime-centered (warp-uniform frame factor ->
                // argmax-neutral; fp error within guard)
                float w0 = v0 ? exp2f((t0 - ctime) * 14.4269504089f) : 0.0f;
                float w1 = v1 ? exp2f((t1 - ctime) * 14.4269504089f) : 0.0f;

                float ssum = w0 + w1;
                #pragma unroll
                for (int o = 16; o; o >>= 1)
                    ssum += __shfl_xor_sync(FULLMASK, ssum, o);
                const float c = EPSf * (ssum + EPSf);

                int bi = -1;

                if (nvalid <= 32) {
                    // ---- COMPACTED: rank-scatter valid element indices
                    // into smem (element order), ONE threefry per lane.
                    const int rank0 = __popc(bL & ltmask) + __popc(bH & ltmask);
                    if (v0) s_d[wwarp][rank0] = d0;
                    if (v1) s_d[wwarp][rank0 + (v0 ? 1 : 0)] = d0 + 1;
                    __syncwarp();
                    const int d = s_d[wwarp][lane < nvalid ? lane : 0];
                    __syncwarp();

                    // fetch w_d from owner lane
                    const float wa = __shfl_sync(FULLMASK, w0, d >> 1);
                    const float wb = __shfl_sync(FULLMASK, w1, d >> 1);
                    const float wd = (d & 1) ? wb : wa;

                    float r = 0.0f;
                    if (lane < nvalid) {
                        const float e = e_from_bits(random_bits_partitionable(
                            ka, kb, ebase64 + (unsigned)d));
                        r = __fdividef(wd + c, e);
                    }

                    const unsigned bmax = __reduce_max_sync(
                        FULLMASK, __float_as_uint(r));
                    const float thr = __uint_as_float(bmax) * (1.0f - REL_GAP);

                    const unsigned bb = __ballot_sync(FULLMASK, r >= thr);
                    // unique in-band winner AND masked elements provably
                    // below the band (r_masked <= c*8.39e6)
                    if (__popc(bb) == 1 && thr > c * MASKED_C_MULT)
                        bi = __shfl_sync(FULLMASK, d, __ffs(bb) - 1);
                } else {
                    // ---- FULL: both elements per lane; masked elements get
                    // r = c/e (exactly the reference surrogate) for free.
                    const float e0 = e_from_bits(random_bits_partitionable(
                        ka, kb, ebase));
                    const float e1 = e_from_bits(random_bits_partitionable(
                        ka, kb, ebase + 1u));
                    const float r0 = __fdividef(w0 + c, e0);
                    const float r1 = __fdividef(w1 + c, e1);

                    const unsigned bmax = __reduce_max_sync(
                        FULLMASK, __float_as_uint(fmaxf(r0, r1)));
                    const float thr = __uint_as_float(bmax) * (1.0f - REL_GAP);

                    const unsigned bb0 = __ballot_sync(FULLMASK, r0 >= thr);
                    const unsigned bb1 = __ballot_sync(FULLMASK, r1 >= thr);
                    if (__popc(bb0) + __popc(bb1) == 1)
                        bi = bb0 ? ((__ffs(bb0) - 1) << 1)
                                 : (((__ffs(bb1) - 1) << 1) | 1);
                }

                if (bi < 0)  // warp-uniform: guard failed -> bit-exact path
                    bi = exact_argmax(t0, t1, v0, v1, ka, kb, ebase, d0);

                // fetch chosen neighbor from its owner lane (bi warp-uniform)
                const int   slot = (bi & 1);
                const int   nid = __shfl_sync(FULLMASK, slot ? ids.y : ids.x, bi >> 1);
                const float nt  = __shfl_sync(FULLMASK, slot ? t1    : t0,   bi >> 1);

                curr = nid;
                ctime = nt;
            }
        }

        if (lane == 0) {
            out_nodes[base + step] = (float)curr;
            out_times[base + step] = ctime;
            out_masks[base + step] = alive ? 1.0f : 0.0f;
        }
    }
}

// ---------------------------------------------------------------------------
extern "C" void kernel_launch(void* const* d_in, const int* in_sizes, int n_in,
                              void* d_out, int out_size)
{
    const int*   src = (const int*)d_in[0];
    const float* ct  = (const float*)d_in[1];
    const int*   nid = (const int*)d_in[2];
    const float* nt  = (const float*)d_in[3];
    const int B = in_sizes[0];

    // fold_in(key(42), step) = threefry2x32((0,42), (0,step))
    StepKeys keys;
    for (int s = 0; s < L_STEPS; s++) { keys.a[s] = 0; keys.b[s] = 0; }
    for (int s = 1; s < L_STEPS; s++) {
        unsigned o0, o1;
        threefry2x32(0u, 42u, 0u, (unsigned)s, o0, o1);
        keys.a[s] = o0; keys.b[s] = o1;
    }

    const int nwalks = B * W_WALKS;
    const int threads = 128;
    const int total_threads = nwalks * 32;
    const int blocks = (total_threads + threads - 1) / threads;

    walk_kernel<<<blocks, threads>>>(src, ct, nid, nt, (float*)d_out, B, keys);
}